// round 15
// baseline (speedup 1.0000x reference)
#include <cuda_runtime.h>
#include <cuda_fp16.h>
#include <cstdint>

#define DINL __device__ __forceinline__

namespace {
constexpr int KDIM = 4096;   // in_features
constexpr int NOUT = 4096;   // out_features
constexpr int MTOK = 1024;   // tokens

constexpr int BM = 128;      // CTA tile M
constexpr int BN = 128;      // CTA tile N
constexpr int BK = 64;       // K per stage (chunk)
constexpr int NUM_K = KDIM / BK;   // 64 (even -> promote-on-odd covers tail)
constexpr int STAGES = 3;
constexpr int THREADS = 128; // 4 warps: 2 in M x 2 in N (64x64 per warp)

constexpr int A_ROW_B = 144;                // 64 halves (128B) + 16B pad -> conflict-free ldmatrix
constexpr int B_ROW_B = 144;
constexpr int A_BYTES = BM * A_ROW_B;       // 18432
constexpr int B_BYTES = BN * B_ROW_B;       // 18432
constexpr int STAGE_BYTES = A_BYTES + B_BYTES;   // 36864
constexpr int LUT_BYTES = 4096;                  // 256 x uint4 (byte -> 8 fp16 {0,1})
constexpr int SMEM_TOTAL = LUT_BYTES + STAGES * STAGE_BYTES;  // 114688 -> 2 CTAs/SM

constexpr int CONV_BLOCKS = (MTOK * KDIM / 16) / 256;           // 1024  (4 float4/thread)
constexpr int PACK_BLOCKS = (NOUT * (KDIM / 256)) / 8;          // 8192  (1 warp = 256 K-values)
}  // namespace

// Scratch (static device globals: allowed; no runtime allocation).
__device__ __align__(16) __half   g_xh[(size_t)MTOK * KDIM];          // 8 MB fp16 x
__device__ __align__(16) unsigned g_wbits[(KDIM / 32) * NOUT];        // 2 MB packed binarized W, [kword][n]

DINL uint32_t smem_u32(const void* p) {
    uint32_t a;
    asm("{ .reg .u64 t; cvta.to.shared.u64 t, %1; cvt.u32.u64 %0, t; }" : "=r"(a) : "l"(p));
    return a;
}

// ---------------- fused prepass: x->fp16  +  binarize/bit-pack W ----------------
__global__ void __launch_bounds__(256) prepass_kernel(const float* __restrict__ x,
                                                      const float* __restrict__ w) {
    if (blockIdx.x < CONV_BLOCKS) {
        // 4 independent float4 per thread (MLP=4)
        int base = blockIdx.x * 256 + threadIdx.x;
        float4 v[4];
        #pragma unroll
        for (int j = 0; j < 4; ++j)
            v[j] = __ldcs((const float4*)x + base + j * (CONV_BLOCKS * 256));
        #pragma unroll
        for (int j = 0; j < 4; ++j) {
            __half2 h0 = __floats2half2_rn(v[j].x, v[j].y);
            __half2 h1 = __floats2half2_rn(v[j].z, v[j].w);
            uint2 u;
            u.x = *(const uint32_t*)&h0;
            u.y = *(const uint32_t*)&h1;
            *(uint2*)(&g_xh[(size_t)(base + j * (CONV_BLOCKS * 256)) * 4]) = u;
        }
    } else {
        // one warp packs 256 K-values (2x float4/lane) of one W row into 8 bit-words
        int pb = blockIdx.x - CONV_BLOCKS;
        int lane = threadIdx.x & 31;
        int wg = pb * 8 + (threadIdx.x >> 5);   // global warp id
        int n = wg & (NOUT - 1);
        int kb = wg >> 12;                      // 256-wide K block, 0..15
        const float4* src = (const float4*)(w + (size_t)n * KDIM + kb * 256);
        const float4 v0 = __ldcs(src + lane);
        const float4 v1 = __ldcs(src + 32 + lane);
        #pragma unroll
        for (int half = 0; half < 2; ++half) {
            const float4& v = half ? v1 : v0;
            unsigned nib = (v.x > 0.f ? 1u : 0u) | (v.y > 0.f ? 2u : 0u)
                         | (v.z > 0.f ? 4u : 0u) | (v.w > 0.f ? 8u : 0u);
            unsigned a = nib | (__shfl_down_sync(0xFFFFFFFFu, nib, 1) << 4);
            unsigned b = a   | (__shfl_down_sync(0xFFFFFFFFu, a, 2)   << 8);
            unsigned m = b   | (__shfl_down_sync(0xFFFFFFFFu, b, 4)   << 16);
            if ((lane & 7) == 0) {
                int c = kb * 8 + half * 4 + (lane >> 3);
                g_wbits[c * NOUT + n] = m;
            }
        }
    }
}

// ---------------- main GEMM: out = (x_fp16 @ Wb^T) * round(max(s,1)) ----------------
// f16-accumulate HMMA; fp32 promotion every 2 chunks (128-K segments) via k8 identity MMA.
// B expanded from 1-bit packed form via a 256-entry smem LUT (byte -> 8 fp16).
__global__ void __launch_bounds__(THREADS, 2)
SBNLinear_39754217292616_kernel(const float* __restrict__ s, float* __restrict__ out) {
    extern __shared__ char smem[];
    const uint32_t sb = smem_u32(smem);          // LUT at [0, 4096)
    const uint32_t stg = sb + LUT_BYTES;         // stages at [4096, ...)
    const int tid = threadIdx.x;
    const int lane = tid & 31;
    const int wid = tid >> 5;                // 0..3
    const int m0 = blockIdx.x * BM;
    const int n0 = blockIdx.y * BN;
    const int m_off = (wid >> 1) * 64;       // 2 warps in M
    const int n_off = (wid & 1) * 64;        // 2 warps in N

    // build LUT: byte e -> 8 fp16 {0,1}
    #pragma unroll
    for (int e = tid; e < 256; e += THREADS) {
        uint4 v;
        v.x = (e & 1u   ? 0x3C00u : 0u) | (e & 2u   ? 0x3C000000u : 0u);
        v.y = (e & 4u   ? 0x3C00u : 0u) | (e & 8u   ? 0x3C000000u : 0u);
        v.z = (e & 16u  ? 0x3C00u : 0u) | (e & 32u  ? 0x3C000000u : 0u);
        v.w = (e & 64u  ? 0x3C00u : 0u) | (e & 128u ? 0x3C000000u : 0u);
        asm volatile("st.shared.v4.b32 [%0], {%1,%2,%3,%4};\n"
                     :: "r"(sb + e * 16), "r"(v.x), "r"(v.y), "r"(v.z), "r"(v.w) : "memory");
    }
    __syncthreads();

    // identity fragment (fp16 I8) for the k8 promotion MMA
    const int q = lane >> 2, p = lane & 3;
    const uint32_t idf = ((2 * p == q) ? 0x3C00u : 0u) | ((2 * p + 1 == q) ? 0x3C000000u : 0u);

    float acc32[4][8][4];
    uint32_t acc16[4][8][2];
    #pragma unroll
    for (int mi = 0; mi < 4; ++mi)
        #pragma unroll
        for (int nj = 0; nj < 8; ++nj) {
            acc16[mi][nj][0] = 0u; acc16[mi][nj][1] = 0u;
            #pragma unroll
            for (int e = 0; e < 4; ++e) acc32[mi][nj][e] = 0.0f;
        }

    auto issueA = [&](int c, int buf) {
        #pragma unroll
        for (int i = 0; i < 8; ++i) {
            int qx = tid + i * THREADS;          // 0..1023
            int row = qx >> 3;
            int ch = qx & 7;
            uint32_t dst = stg + buf * STAGE_BYTES + row * A_ROW_B + ch * 16;
            const __half* src = &g_xh[(size_t)(m0 + row) * KDIM + c * BK + ch * 8];
            asm volatile("cp.async.cg.shared.global [%0], [%1], 16;\n" :: "r"(dst), "l"(src) : "memory");
        }
    };
    // one thread per B row: 8 bytes -> 8 LUT gathers -> 128B of fp16 {0,1}
    auto stsB = [&](uint2 bits, int buf) {
        uint32_t dst = stg + buf * STAGE_BYTES + A_BYTES + tid * B_ROW_B;
        #pragma unroll
        for (int j = 0; j < 8; ++j) {
            unsigned b8 = ((j < 4 ? bits.x : bits.y) >> ((j & 3) * 8)) & 0xFFu;
            uint32_t r0, r1, r2, r3;
            asm volatile("ld.shared.v4.b32 {%0,%1,%2,%3}, [%4];\n"
                         : "=r"(r0), "=r"(r1), "=r"(r2), "=r"(r3) : "r"(sb + b8 * 16));
            asm volatile("st.shared.v4.b32 [%0], {%1,%2,%3,%4};\n"
                         :: "r"(dst + j * 16), "r"(r0), "r"(r1), "r"(r2), "r"(r3) : "memory");
        }
    };
    auto loadBits = [&](int c) -> uint2 {
        uint2 r;
        r.x = g_wbits[(2 * c) * NOUT + n0 + tid];
        r.y = g_wbits[(2 * c + 1) * NOUT + n0 + tid];
        return r;
    };

    // prologue: stages 0..1
    #pragma unroll
    for (int c = 0; c < STAGES - 1; ++c) {
        issueA(c, c);
        asm volatile("cp.async.commit_group;\n" ::: "memory");
        stsB(loadBits(c), c);
    }
    uint2 bits_next = loadBits(2);

    for (int c = 0; c < NUM_K; ++c) {
        const int buf = c % 3;
        if (c < NUM_K - 2) asm volatile("cp.async.wait_group 1;\n" ::: "memory");
        else               asm volatile("cp.async.wait_group 0;\n" ::: "memory");
        __syncthreads();

        const int cn = c + 2;
        if (cn < NUM_K) {
            const int nbuf = cn % 3;
            stsB(bits_next, nbuf);
            issueA(cn, nbuf);
            asm volatile("cp.async.commit_group;\n" ::: "memory");
            if (cn + 1 < NUM_K)
                bits_next = loadBits(cn + 1);
        }

        const uint32_t ab = stg + buf * STAGE_BYTES;
        const uint32_t bb = ab + A_BYTES;
        #pragma unroll
        for (int h = 0; h < 4; ++h) {
            uint32_t a[4][4];
            #pragma unroll
            for (int mi = 0; mi < 4; ++mi) {
                uint32_t addr = ab + (uint32_t)(m_off + 16 * mi + (lane & 15)) * A_ROW_B
                                   + (uint32_t)(2 * h + (lane >> 4)) * 16;
                asm volatile("ldmatrix.sync.aligned.m8n8.x4.shared.b16 {%0,%1,%2,%3}, [%4];\n"
                             : "=r"(a[mi][0]), "=r"(a[mi][1]), "=r"(a[mi][2]), "=r"(a[mi][3])
                             : "r"(addr));
            }
            #pragma unroll
            for (int g = 0; g < 4; ++g) {
                int row = n_off + 16 * g + ((lane >> 4) << 3) + (lane & 7);
                uint32_t addr = bb + (uint32_t)row * B_ROW_B
                                   + (uint32_t)(2 * h + ((lane >> 3) & 1)) * 16;
                uint32_t r0, r1, r2, r3;
                asm volatile("ldmatrix.sync.aligned.m8n8.x4.shared.b16 {%0,%1,%2,%3}, [%4];\n"
                             : "=r"(r0), "=r"(r1), "=r"(r2), "=r"(r3) : "r"(addr));
                #pragma unroll
                for (int mi = 0; mi < 4; ++mi) {
                    asm volatile(
                        "mma.sync.aligned.m16n8k16.row.col.f16.f16.f16.f16 "
                        "{%0,%1}, {%2,%3,%4,%5}, {%6,%7}, {%0,%1};\n"
                        : "+r"(acc16[mi][2 * g][0]), "+r"(acc16[mi][2 * g][1])
                        : "r"(a[mi][0]), "r"(a[mi][1]), "r"(a[mi][2]), "r"(a[mi][3]),
                          "r"(r0), "r"(r1));
                    asm volatile(
                        "mma.sync.aligned.m16n8k16.row.col.f16.f16.f16.f16 "
                        "{%0,%1}, {%2,%3,%4,%5}, {%6,%7}, {%0,%1};\n"
                        : "+r"(acc16[mi][2 * g + 1][0]), "+r"(acc16[mi][2 * g + 1][1])
                        : "r"(a[mi][0]), "r"(a[mi][1]), "r"(a[mi][2]), "r"(a[mi][3]),
                          "r"(r2), "r"(r3));
                }
            }
        }

        // promote f16 segment accumulators (128 K-steps) into fp32 every 2 chunks
        if (c & 1) {
            #pragma unroll
            for (int mi = 0; mi < 4; ++mi)
                #pragma unroll
                for (int nj = 0; nj < 8; ++nj) {
                    asm volatile(
                        "mma.sync.aligned.m16n8k8.row.col.f32.f16.f16.f32 "
                        "{%0,%1,%2,%3}, {%4,%5}, {%6}, {%0,%1,%2,%3};\n"
                        : "+f"(acc32[mi][nj][0]), "+f"(acc32[mi][nj][1]),
                          "+f"(acc32[mi][nj][2]), "+f"(acc32[mi][nj][3])
                        : "r"(acc16[mi][nj][0]), "r"(acc16[mi][nj][1]), "r"(idf));
                    acc16[mi][nj][0] = 0u;
                    acc16[mi][nj][1] = 0u;
                }
        }
    }

    // epilogue: fuse s_eff = rint(max(s,1)) and store
    float sc[8][2];
    #pragma unroll
    for (int nj = 0; nj < 8; ++nj) {
        int col = n0 + n_off + 8 * nj + 2 * (lane & 3);
        sc[nj][0] = rintf(fmaxf(s[col], 1.0f));
        sc[nj][1] = rintf(fmaxf(s[col + 1], 1.0f));
    }
    #pragma unroll
    for (int mi = 0; mi < 4; ++mi) {
        int r0 = m0 + m_off + 16 * mi + (lane >> 2);
        #pragma unroll
        for (int nj = 0; nj < 8; ++nj) {
            int col = n0 + n_off + 8 * nj + 2 * (lane & 3);
            float2 v0 = make_float2(acc32[mi][nj][0] * sc[nj][0], acc32[mi][nj][1] * sc[nj][1]);
            float2 v1 = make_float2(acc32[mi][nj][2] * sc[nj][0], acc32[mi][nj][3] * sc[nj][1]);
            *(float2*)(out + (size_t)r0 * NOUT + col) = v0;
            *(float2*)(out + (size_t)(r0 + 8) * NOUT + col) = v1;
        }
    }
}

extern "C" void kernel_launch(void* const* d_in, const int* in_sizes, int n_in,
                              void* d_out, int out_size) {
    (void)in_sizes; (void)n_in; (void)out_size;
    const float* x = (const float*)d_in[0];
    const float* w = (const float*)d_in[1];
    const float* s = (const float*)d_in[2];
    float* out = (float*)d_out;

    prepass_kernel<<<CONV_BLOCKS + PACK_BLOCKS, 256>>>(x, w);

    cudaFuncSetAttribute(SBNLinear_39754217292616_kernel,
                         cudaFuncAttributeMaxDynamicSharedMemorySize, SMEM_TOTAL);
    dim3 grid(MTOK / BM, NOUT / BN);   // 8 x 32 = 256 CTAs, 2 resident/SM
    SBNLinear_39754217292616_kernel<<<grid, THREADS, SMEM_TOTAL>>>(s, out);
}

// round 16
// speedup vs baseline: 1.1199x; 1.1199x over previous
#include <cuda_runtime.h>
#include <cuda_fp16.h>
#include <cstdint>

#define DINL __device__ __forceinline__

namespace {
constexpr int KDIM = 4096;   // in_features
constexpr int NOUT = 4096;   // out_features
constexpr int MTOK = 1024;   // tokens

constexpr int BM = 128;      // CTA tile M
constexpr int BN = 128;      // CTA tile N
constexpr int BK = 64;       // K per stage (chunk)
constexpr int NUM_K = KDIM / BK;   // 64
constexpr int STAGES = 3;
constexpr int THREADS = 128; // 4 warps: 2 in M x 2 in N (64x64 per warp)

constexpr int A_ROW_B = 144;                // 64 halves (128B) + 16B pad -> conflict-free ldmatrix
constexpr int B_ROW_B = 144;
constexpr int A_BYTES = BM * A_ROW_B;       // 18432
constexpr int B_BYTES = BN * B_ROW_B;       // 18432
constexpr int STAGE_BYTES = A_BYTES + B_BYTES;   // 36864
constexpr int LUT_BYTES = 4096;                  // 256 x uint4 (byte -> 8 fp16 {0,1})
constexpr int SMEM_TOTAL = LUT_BYTES + STAGES * STAGE_BYTES;  // 114688 -> 2 CTAs/SM

constexpr int CONV_BLOCKS = (MTOK * KDIM / 16) / 256;           // 1024  (4 float4/thread)
constexpr int PACK_BLOCKS = (NOUT * (KDIM / 256)) / 8;          // 8192  (1 warp = 256 K-values)
}  // namespace

// Scratch (static device globals: allowed; no runtime allocation).
__device__ __align__(16) __half   g_xh[(size_t)MTOK * KDIM];          // 8 MB fp16 x
__device__ __align__(16) unsigned g_wbits[(KDIM / 32) * NOUT];        // 2 MB packed binarized W, [kword][n]

DINL uint32_t smem_u32(const void* p) {
    uint32_t a;
    asm("{ .reg .u64 t; cvta.to.shared.u64 t, %1; cvt.u32.u64 %0, t; }" : "=r"(a) : "l"(p));
    return a;
}

// ---------------- fused prepass: x->fp16  +  binarize/bit-pack W ----------------
__global__ void __launch_bounds__(256) prepass_kernel(const float* __restrict__ x,
                                                      const float* __restrict__ w) {
    if (blockIdx.x < CONV_BLOCKS) {
        // 4 independent float4 per thread (MLP=4)
        int base = blockIdx.x * 256 + threadIdx.x;
        float4 v[4];
        #pragma unroll
        for (int j = 0; j < 4; ++j)
            v[j] = __ldcs((const float4*)x + base + j * (CONV_BLOCKS * 256));
        #pragma unroll
        for (int j = 0; j < 4; ++j) {
            __half2 h0 = __floats2half2_rn(v[j].x, v[j].y);
            __half2 h1 = __floats2half2_rn(v[j].z, v[j].w);
            uint2 u;
            u.x = *(const uint32_t*)&h0;
            u.y = *(const uint32_t*)&h1;
            *(uint2*)(&g_xh[(size_t)(base + j * (CONV_BLOCKS * 256)) * 4]) = u;
        }
    } else {
        // one warp packs 256 K-values (2x float4/lane) of one W row into 8 bit-words
        int pb = blockIdx.x - CONV_BLOCKS;
        int lane = threadIdx.x & 31;
        int wg = pb * 8 + (threadIdx.x >> 5);   // global warp id
        int n = wg & (NOUT - 1);
        int kb = wg >> 12;                      // 256-wide K block, 0..15
        const float4* src = (const float4*)(w + (size_t)n * KDIM + kb * 256);
        const float4 v0 = __ldcs(src + lane);
        const float4 v1 = __ldcs(src + 32 + lane);
        #pragma unroll
        for (int half = 0; half < 2; ++half) {
            const float4& v = half ? v1 : v0;
            unsigned nib = (v.x > 0.f ? 1u : 0u) | (v.y > 0.f ? 2u : 0u)
                         | (v.z > 0.f ? 4u : 0u) | (v.w > 0.f ? 8u : 0u);
            unsigned a = nib | (__shfl_down_sync(0xFFFFFFFFu, nib, 1) << 4);
            unsigned b = a   | (__shfl_down_sync(0xFFFFFFFFu, a, 2)   << 8);
            unsigned m = b   | (__shfl_down_sync(0xFFFFFFFFu, b, 4)   << 16);
            if ((lane & 7) == 0) {
                int c = kb * 8 + half * 4 + (lane >> 3);
                g_wbits[c * NOUT + n] = m;
            }
        }
    }
}

// ---------------- main GEMM: out = (x_fp16 @ Wb^T) * round(max(s,1)) ----------------
// f16-accumulate HMMA; fp32 promotion per 64-K segment via k8 identity MMA.
// B expanded via 256-entry smem LUT. Staging (stsB/cp.async) moved AFTER the MMA
// loop so MIO in-order issue doesn't delay the chunk's first ldmatrix.
__global__ void __launch_bounds__(THREADS, 2)
SBNLinear_39754217292616_kernel(const float* __restrict__ s, float* __restrict__ out) {
    extern __shared__ char smem[];
    const uint32_t sb = smem_u32(smem);          // LUT at [0, 4096)
    const uint32_t stg = sb + LUT_BYTES;         // stages at [4096, ...)
    const int tid = threadIdx.x;
    const int lane = tid & 31;
    const int wid = tid >> 5;                // 0..3
    const int m0 = blockIdx.x * BM;
    const int n0 = blockIdx.y * BN;
    const int m_off = (wid >> 1) * 64;       // 2 warps in M
    const int n_off = (wid & 1) * 64;        // 2 warps in N

    // build LUT: byte e -> 8 fp16 {0,1}
    #pragma unroll
    for (int e = tid; e < 256; e += THREADS) {
        uint4 v;
        v.x = (e & 1u   ? 0x3C00u : 0u) | (e & 2u   ? 0x3C000000u : 0u);
        v.y = (e & 4u   ? 0x3C00u : 0u) | (e & 8u   ? 0x3C000000u : 0u);
        v.z = (e & 16u  ? 0x3C00u : 0u) | (e & 32u  ? 0x3C000000u : 0u);
        v.w = (e & 64u  ? 0x3C00u : 0u) | (e & 128u ? 0x3C000000u : 0u);
        asm volatile("st.shared.v4.b32 [%0], {%1,%2,%3,%4};\n"
                     :: "r"(sb + e * 16), "r"(v.x), "r"(v.y), "r"(v.z), "r"(v.w) : "memory");
    }
    __syncthreads();

    // identity fragment (fp16 I8) for the k8 promotion MMA
    const int q = lane >> 2, p = lane & 3;
    const uint32_t idf = ((2 * p == q) ? 0x3C00u : 0u) | ((2 * p + 1 == q) ? 0x3C000000u : 0u);

    float acc32[4][8][4];
    uint32_t acc16[4][8][2];
    #pragma unroll
    for (int mi = 0; mi < 4; ++mi)
        #pragma unroll
        for (int nj = 0; nj < 8; ++nj) {
            acc16[mi][nj][0] = 0u; acc16[mi][nj][1] = 0u;
            #pragma unroll
            for (int e = 0; e < 4; ++e) acc32[mi][nj][e] = 0.0f;
        }

    auto issueA = [&](int c, int buf) {
        #pragma unroll
        for (int i = 0; i < 8; ++i) {
            int qx = tid + i * THREADS;          // 0..1023
            int row = qx >> 3;
            int ch = qx & 7;
            uint32_t dst = stg + buf * STAGE_BYTES + row * A_ROW_B + ch * 16;
            const __half* src = &g_xh[(size_t)(m0 + row) * KDIM + c * BK + ch * 8];
            asm volatile("cp.async.cg.shared.global [%0], [%1], 16;\n" :: "r"(dst), "l"(src) : "memory");
        }
    };
    // one thread per B row: 8 bytes -> 8 LUT gathers -> 128B of fp16 {0,1}
    auto stsB = [&](uint2 bits, int buf) {
        uint32_t dst = stg + buf * STAGE_BYTES + A_BYTES + tid * B_ROW_B;
        #pragma unroll
        for (int j = 0; j < 8; ++j) {
            unsigned b8 = ((j < 4 ? bits.x : bits.y) >> ((j & 3) * 8)) & 0xFFu;
            uint32_t r0, r1, r2, r3;
            asm volatile("ld.shared.v4.b32 {%0,%1,%2,%3}, [%4];\n"
                         : "=r"(r0), "=r"(r1), "=r"(r2), "=r"(r3) : "r"(sb + b8 * 16));
            asm volatile("st.shared.v4.b32 [%0], {%1,%2,%3,%4};\n"
                         :: "r"(dst + j * 16), "r"(r0), "r"(r1), "r"(r2), "r"(r3) : "memory");
        }
    };
    auto loadBits = [&](int c) -> uint2 {
        uint2 r;
        r.x = g_wbits[(2 * c) * NOUT + n0 + tid];
        r.y = g_wbits[(2 * c + 1) * NOUT + n0 + tid];
        return r;
    };

    // prologue: stages 0..1
    #pragma unroll
    for (int c = 0; c < STAGES - 1; ++c) {
        issueA(c, c);
        asm volatile("cp.async.commit_group;\n" ::: "memory");
        stsB(loadBits(c), c);
    }
    uint2 bits_next = loadBits(2);

    for (int c = 0; c < NUM_K; ++c) {
        const int buf = c % 3;
        if (c < NUM_K - 2) asm volatile("cp.async.wait_group 1;\n" ::: "memory");
        else               asm volatile("cp.async.wait_group 0;\n" ::: "memory");
        __syncthreads();

        // ---- compute first: MMAs start immediately off the barrier ----
        const uint32_t ab = stg + buf * STAGE_BYTES;
        const uint32_t bb = ab + A_BYTES;
        #pragma unroll
        for (int h = 0; h < 4; ++h) {
            uint32_t a[4][4];
            #pragma unroll
            for (int mi = 0; mi < 4; ++mi) {
                uint32_t addr = ab + (uint32_t)(m_off + 16 * mi + (lane & 15)) * A_ROW_B
                                   + (uint32_t)(2 * h + (lane >> 4)) * 16;
                asm volatile("ldmatrix.sync.aligned.m8n8.x4.shared.b16 {%0,%1,%2,%3}, [%4];\n"
                             : "=r"(a[mi][0]), "=r"(a[mi][1]), "=r"(a[mi][2]), "=r"(a[mi][3])
                             : "r"(addr));
            }
            #pragma unroll
            for (int g = 0; g < 4; ++g) {
                int row = n_off + 16 * g + ((lane >> 4) << 3) + (lane & 7);
                uint32_t addr = bb + (uint32_t)row * B_ROW_B
                                   + (uint32_t)(2 * h + ((lane >> 3) & 1)) * 16;
                uint32_t r0, r1, r2, r3;
                asm volatile("ldmatrix.sync.aligned.m8n8.x4.shared.b16 {%0,%1,%2,%3}, [%4];\n"
                             : "=r"(r0), "=r"(r1), "=r"(r2), "=r"(r3) : "r"(addr));
                #pragma unroll
                for (int mi = 0; mi < 4; ++mi) {
                    asm volatile(
                        "mma.sync.aligned.m16n8k16.row.col.f16.f16.f16.f16 "
                        "{%0,%1}, {%2,%3,%4,%5}, {%6,%7}, {%0,%1};\n"
                        : "+r"(acc16[mi][2 * g][0]), "+r"(acc16[mi][2 * g][1])
                        : "r"(a[mi][0]), "r"(a[mi][1]), "r"(a[mi][2]), "r"(a[mi][3]),
                          "r"(r0), "r"(r1));
                    asm volatile(
                        "mma.sync.aligned.m16n8k16.row.col.f16.f16.f16.f16 "
                        "{%0,%1}, {%2,%3,%4,%5}, {%6,%7}, {%0,%1};\n"
                        : "+r"(acc16[mi][2 * g + 1][0]), "+r"(acc16[mi][2 * g + 1][1])
                        : "r"(a[mi][0]), "r"(a[mi][1]), "r"(a[mi][2]), "r"(a[mi][3]),
                          "r"(r2), "r"(r3));
                }
            }
        }

        // promote f16 segment accumulators (64 K-steps) into fp32 on the tensor pipe
        #pragma unroll
        for (int mi = 0; mi < 4; ++mi)
            #pragma unroll
            for (int nj = 0; nj < 8; ++nj) {
                asm volatile(
                    "mma.sync.aligned.m16n8k8.row.col.f32.f16.f16.f32 "
                    "{%0,%1,%2,%3}, {%4,%5}, {%6}, {%0,%1,%2,%3};\n"
                    : "+f"(acc32[mi][nj][0]), "+f"(acc32[mi][nj][1]),
                      "+f"(acc32[mi][nj][2]), "+f"(acc32[mi][nj][3])
                    : "r"(acc16[mi][nj][0]), "r"(acc16[mi][nj][1]), "r"(idf));
                acc16[mi][nj][0] = 0u;
                acc16[mi][nj][1] = 0u;
            }

        // ---- staging last: fills the tail toward the next barrier ----
        const int cn = c + 2;
        if (cn < NUM_K) {
            const int nbuf = cn % 3;
            stsB(bits_next, nbuf);
            issueA(cn, nbuf);
            asm volatile("cp.async.commit_group;\n" ::: "memory");
            if (cn + 1 < NUM_K)
                bits_next = loadBits(cn + 1);
        }
    }

    // epilogue: fuse s_eff = rint(max(s,1)) and store
    float sc[8][2];
    #pragma unroll
    for (int nj = 0; nj < 8; ++nj) {
        int col = n0 + n_off + 8 * nj + 2 * (lane & 3);
        sc[nj][0] = rintf(fmaxf(s[col], 1.0f));
        sc[nj][1] = rintf(fmaxf(s[col + 1], 1.0f));
    }
    #pragma unroll
    for (int mi = 0; mi < 4; ++mi) {
        int r0 = m0 + m_off + 16 * mi + (lane >> 2);
        #pragma unroll
        for (int nj = 0; nj < 8; ++nj) {
            int col = n0 + n_off + 8 * nj + 2 * (lane & 3);
            float2 v0 = make_float2(acc32[mi][nj][0] * sc[nj][0], acc32[mi][nj][1] * sc[nj][1]);
            float2 v1 = make_float2(acc32[mi][nj][2] * sc[nj][0], acc32[mi][nj][3] * sc[nj][1]);
            *(float2*)(out + (size_t)r0 * NOUT + col) = v0;
            *(float2*)(out + (size_t)(r0 + 8) * NOUT + col) = v1;
        }
    }
}

extern "C" void kernel_launch(void* const* d_in, const int* in_sizes, int n_in,
                              void* d_out, int out_size) {
    (void)in_sizes; (void)n_in; (void)out_size;
    const float* x = (const float*)d_in[0];
    const float* w = (const float*)d_in[1];
    const float* s = (const float*)d_in[2];
    float* out = (float*)d_out;

    prepass_kernel<<<CONV_BLOCKS + PACK_BLOCKS, 256>>>(x, w);

    cudaFuncSetAttribute(SBNLinear_39754217292616_kernel,
                         cudaFuncAttributeMaxDynamicSharedMemorySize, SMEM_TOTAL);
    dim3 grid(MTOK / BM, NOUT / BN);   // 8 x 32 = 256 CTAs, 2 resident/SM
    SBNLinear_39754217292616_kernel<<<grid, THREADS, SMEM_TOTAL>>>(s, out);
}